// round 2
// baseline (speedup 1.0000x reference)
#include <cuda_runtime.h>
#include <cuda_bf16.h>
#include <cuda_fp16.h>
#include <cstdint>

// Problem shape (fixed by the dataset)
#define BATCH 8
#define LSEQ  2048
#define DDIM  1024
#define TAW_INV 50.0f

// Scratch (static __device__ arrays — allocation-free rule)
__device__ __nv_bfloat16 g_Qb[(size_t)BATCH * LSEQ * DDIM];   // 33.5 MB
__device__ __nv_bfloat16 g_Mb[(size_t)BATCH * LSEQ * DDIM];   // 33.5 MB
__device__ __half        g_S [(size_t)BATCH * LSEQ * LSEQ];   // 67 MB (raw dots, no *50)

// ---------------------------------------------------------------------------
// Kernel 1: fp32 -> bf16 conversion of query and memory
// ---------------------------------------------------------------------------
__global__ void convert_kernel(const float* __restrict__ q, const float* __restrict__ m) {
    size_t i = (size_t)blockIdx.x * blockDim.x + threadIdx.x;   // index over float4s
    size_t n4 = (size_t)BATCH * LSEQ * DDIM / 4;
    if (i >= n4) return;
    float4 vq = ((const float4*)q)[i];
    float4 vm = ((const float4*)m)[i];
    __nv_bfloat162* Q2 = (__nv_bfloat162*)g_Qb;
    __nv_bfloat162* M2 = (__nv_bfloat162*)g_Mb;
    Q2[2*i]   = __nv_bfloat162(__float2bfloat16(vq.x), __float2bfloat16(vq.y));
    Q2[2*i+1] = __nv_bfloat162(__float2bfloat16(vq.z), __float2bfloat16(vq.w));
    M2[2*i]   = __nv_bfloat162(__float2bfloat16(vm.x), __float2bfloat16(vm.y));
    M2[2*i+1] = __nv_bfloat162(__float2bfloat16(vm.z), __float2bfloat16(vm.w));
}

// ---------------------------------------------------------------------------
// Kernel 2: approximate scores S[b,q,k] = dot(Q[b,q,:], M[b,k,:]) in bf16 MMA
// Tiled GEMM, mma.sync.m16n8k16.bf16, cp.async 2-stage pipeline.
// ---------------------------------------------------------------------------
#define BM 128
#define BN 128
#define BK 32
#define LDS_T 40   // BK + 8 pad (80B rows: 16B-aligned, conflict-dodging)

__device__ __forceinline__ void cp_async16(void* smem, const void* gptr) {
    uint32_t s = (uint32_t)__cvta_generic_to_shared(smem);
    asm volatile("cp.async.cg.shared.global [%0], [%1], 16;\n" :: "r"(s), "l"(gptr));
}

#define MMA16816(d, a, b)                                                     \
    asm volatile(                                                             \
        "mma.sync.aligned.m16n8k16.row.col.f32.bf16.bf16.f32 "                \
        "{%0,%1,%2,%3}, {%4,%5,%6,%7}, {%8,%9}, {%0,%1,%2,%3};\n"             \
        : "+f"((d)[0]), "+f"((d)[1]), "+f"((d)[2]), "+f"((d)[3])              \
        : "r"((a)[0]), "r"((a)[1]), "r"((a)[2]), "r"((a)[3]),                 \
          "r"((b)[0]), "r"((b)[1]))

__global__ __launch_bounds__(256) void qk_gemm_kernel() {
    __shared__ __nv_bfloat16 As[2][BM][LDS_T];
    __shared__ __nv_bfloat16 Bs[2][BN][LDS_T];

    const int tid   = threadIdx.x;
    const int b     = blockIdx.z;
    const int mBase = blockIdx.y * BM;
    const int nBase = blockIdx.x * BN;

    const __nv_bfloat16* Qb = g_Qb + (size_t)b * LSEQ * DDIM;
    const __nv_bfloat16* Mb = g_Mb + (size_t)b * LSEQ * DDIM;

    const int lane  = tid & 31;
    const int warp  = tid >> 5;
    const int warpM = warp >> 2;      // 0..1  -> 64-row stripe
    const int warpN = warp & 3;       // 0..3  -> 32-col stripe
    const int g     = lane >> 2;      // group id 0..7
    const int t     = lane & 3;       // thread in group 0..3

    float acc[4][4][4];
    #pragma unroll
    for (int i = 0; i < 4; i++)
        #pragma unroll
        for (int j = 0; j < 4; j++)
            #pragma unroll
            for (int r = 0; r < 4; r++) acc[i][j][r] = 0.f;

    auto stage_load = [&](int stage, int kb) {
        int k0 = kb * BK;
        #pragma unroll
        for (int h = 0; h < 2; h++) {
            int j = tid + h * 256;          // 0..511 chunk id (16B chunks)
            int row = j >> 2;
            int c   = (j & 3) * 8;
            cp_async16(&As[stage][row][c], Qb + (size_t)(mBase + row) * DDIM + k0 + c);
            cp_async16(&Bs[stage][row][c], Mb + (size_t)(nBase + row) * DDIM + k0 + c);
        }
        asm volatile("cp.async.commit_group;\n");
    };

    const int NKB = DDIM / BK;   // 32
    stage_load(0, 0);

    for (int kb = 0; kb < NKB; kb++) {
        int cur = kb & 1;
        if (kb + 1 < NKB) {
            stage_load(cur ^ 1, kb + 1);
            asm volatile("cp.async.wait_group 1;\n");
        } else {
            asm volatile("cp.async.wait_group 0;\n");
        }
        __syncthreads();

        const __nv_bfloat16* Ab = &As[cur][0][0];
        const __nv_bfloat16* Bb = &Bs[cur][0][0];
        #pragma unroll
        for (int ks = 0; ks < 2; ks++) {
            uint32_t afr[4][4], bfr[4][2];
            const int cK = ks * 16 + 2 * t;
            #pragma unroll
            for (int mt = 0; mt < 4; mt++) {
                int r = warpM * 64 + mt * 16 + g;
                afr[mt][0] = *(const uint32_t*)(Ab + (r    ) * LDS_T + cK    );
                afr[mt][1] = *(const uint32_t*)(Ab + (r + 8) * LDS_T + cK    );
                afr[mt][2] = *(const uint32_t*)(Ab + (r    ) * LDS_T + cK + 8);
                afr[mt][3] = *(const uint32_t*)(Ab + (r + 8) * LDS_T + cK + 8);
            }
            #pragma unroll
            for (int nt = 0; nt < 4; nt++) {
                int r = warpN * 32 + nt * 8 + g;
                bfr[nt][0] = *(const uint32_t*)(Bb + r * LDS_T + cK    );
                bfr[nt][1] = *(const uint32_t*)(Bb + r * LDS_T + cK + 8);
            }
            #pragma unroll
            for (int mt = 0; mt < 4; mt++)
                #pragma unroll
                for (int nt = 0; nt < 4; nt++)
                    MMA16816(acc[mt][nt], afr[mt], bfr[nt]);
        }
        __syncthreads();
    }

    // Epilogue: write raw dot scores as fp16
    __half* Srow = g_S + (size_t)b * LSEQ * LSEQ;
    #pragma unroll
    for (int mt = 0; mt < 4; mt++) {
        #pragma unroll
        for (int nt = 0; nt < 4; nt++) {
            int row = mBase + warpM * 64 + mt * 16 + g;
            int col = nBase + warpN * 32 + nt * 8 + 2 * t;
            *(half2*)(Srow + (size_t)(row    ) * LSEQ + col) =
                __floats2half2_rn(acc[mt][nt][0], acc[mt][nt][1]);
            *(half2*)(Srow + (size_t)(row + 8) * LSEQ + col) =
                __floats2half2_rn(acc[mt][nt][2], acc[mt][nt][3]);
        }
    }
}

// ---------------------------------------------------------------------------
// Kernel 3: per-row refine. Find approx max, collect candidates within
// 1.0 dot units (= 50 logits), recompute exact fp32 dots, exact softmax
// over candidates, write mixture of memory rows.
// ---------------------------------------------------------------------------
#define CAP 64
#define MARGIN 1.0f

__global__ __launch_bounds__(256) void refine_kernel(const float* __restrict__ Q,
                                                     const float* __restrict__ Mem,
                                                     float* __restrict__ Out) {
    const int b = blockIdx.y, q = blockIdx.x, tid = threadIdx.x;
    const __half* srow = g_S + ((size_t)b * LSEQ + q) * LSEQ;

    __shared__ float red[8];
    __shared__ int   s_cnt;
    __shared__ int   s_idx[CAP];
    __shared__ float s_dot[CAP];
    __shared__ float s_w[CAP];
    __shared__ float s_max;

    // 1) row max of approx scores
    float mx = -1e30f;
    for (int k = tid; k < LSEQ; k += 256) mx = fmaxf(mx, __half2float(srow[k]));
    #pragma unroll
    for (int o = 16; o; o >>= 1) mx = fmaxf(mx, __shfl_xor_sync(0xffffffffu, mx, o));
    if ((tid & 31) == 0) red[tid >> 5] = mx;
    __syncthreads();
    if (tid < 32) {
        float v = (tid < 8) ? red[tid] : -1e30f;
        #pragma unroll
        for (int o = 4; o; o >>= 1) v = fmaxf(v, __shfl_xor_sync(0xffffffffu, v, o));
        if (tid == 0) { s_max = v; s_cnt = 0; }
    }
    __syncthreads();

    // 2) candidate collection
    float thr = s_max - MARGIN;
    for (int k = tid; k < LSEQ; k += 256) {
        if (__half2float(srow[k]) >= thr) {
            int p = atomicAdd(&s_cnt, 1);
            if (p < CAP) s_idx[p] = k;
        }
    }
    __syncthreads();
    int nc = min(s_cnt, CAP);
    if (tid == 0) {  // sort for determinism
        for (int i = 1; i < nc; i++) {
            int v = s_idx[i], j = i - 1;
            while (j >= 0 && s_idx[j] > v) { s_idx[j + 1] = s_idx[j]; j--; }
            s_idx[j + 1] = v;
        }
    }
    __syncthreads();

    // 3) exact fp32 dots for candidates
    const float* qrow = Q + ((size_t)b * LSEQ + q) * DDIM;
    for (int j = 0; j < nc; j++) {
        const float* mrow = Mem + ((size_t)b * LSEQ + s_idx[j]) * DDIM;
        float p = 0.f;
        for (int d = tid; d < DDIM; d += 256) p += qrow[d] * mrow[d];
        #pragma unroll
        for (int o = 16; o; o >>= 1) p += __shfl_xor_sync(0xffffffffu, p, o);
        __syncthreads();
        if ((tid & 31) == 0) red[tid >> 5] = p;
        __syncthreads();
        if (tid == 0) {
            float s = 0.f;
            #pragma unroll
            for (int w = 0; w < 8; w++) s += red[w];
            s_dot[j] = s;
        }
    }
    __syncthreads();

    // 4) exact softmax over candidates
    if (tid == 0) {
        float dm = -1e30f;
        for (int j = 0; j < nc; j++) dm = fmaxf(dm, s_dot[j]);
        float sum = 0.f;
        for (int j = 0; j < nc; j++) {
            float w = expf((s_dot[j] - dm) * TAW_INV);
            s_w[j] = w; sum += w;
        }
        float inv = 1.0f / sum;
        for (int j = 0; j < nc; j++) s_w[j] *= inv;
    }
    __syncthreads();

    // 5) output mixture
    float* orow = Out + ((size_t)b * LSEQ + q) * DDIM;
    for (int d = tid; d < DDIM; d += 256) {
        float a = 0.f;
        for (int j = 0; j < nc; j++)
            a += s_w[j] * Mem[((size_t)b * LSEQ + s_idx[j]) * DDIM + d];
        orow[d] = a;
    }
}

// ---------------------------------------------------------------------------
extern "C" void kernel_launch(void* const* d_in, const int* in_sizes, int n_in,
                              void* d_out, int out_size) {
    const float* q = (const float*)d_in[0];
    const float* m = (const float*)d_in[1];
    float* out = (float*)d_out;

    size_t n4 = (size_t)BATCH * LSEQ * DDIM / 4;           // 4,194,304
    convert_kernel<<<(unsigned)((n4 + 255) / 256), 256>>>(q, m);

    dim3 gg(LSEQ / BN, LSEQ / BM, BATCH);                  // 16 x 16 x 8
    qk_gemm_kernel<<<gg, 256>>>();

    dim3 rg(LSEQ, BATCH);                                  // per (q, b) row
    refine_kernel<<<rg, 256>>>(q, m, out);
}

// round 6
// speedup vs baseline: 1.1075x; 1.1075x over previous
#include <cuda_runtime.h>
#include <cuda_bf16.h>
#include <cuda_fp16.h>
#include <cstdint>

// Problem shape (fixed by the dataset)
#define BATCH 8
#define LSEQ  2048
#define DDIM  1024
#define TAW_INV 50.0f

// Scratch (static __device__ arrays — allocation-free rule)
__device__ __nv_bfloat16 g_Qb[(size_t)BATCH * LSEQ * DDIM];   // 33.5 MB
__device__ __nv_bfloat16 g_Mb[(size_t)BATCH * LSEQ * DDIM];   // 33.5 MB
__device__ __half        g_S [(size_t)BATCH * LSEQ * LSEQ];   // 67 MB (raw dots)

// ---------------------------------------------------------------------------
// Helpers
// ---------------------------------------------------------------------------
__device__ __forceinline__ uint32_t smem_u32(const void* p) {
    uint32_t a;
    asm("{ .reg .u64 t; cvta.to.shared.u64 t, %1; cvt.u32.u64 %0, t; }"
        : "=r"(a) : "l"(p));
    return a;
}

__device__ __forceinline__ void cp_async16(uint32_t saddr, const void* gptr) {
    asm volatile("cp.async.cg.shared.global [%0], [%1], 16;\n" :: "r"(saddr), "l"(gptr));
}

#define LDSM_X4(r, addr) \
    asm volatile("ldmatrix.sync.aligned.m8n8.x4.shared.b16 {%0,%1,%2,%3}, [%4];" \
        : "=r"((r)[0]), "=r"((r)[1]), "=r"((r)[2]), "=r"((r)[3]) : "r"(addr))

#define MMA16816(d, a, b)                                                     \
    asm volatile(                                                             \
        "mma.sync.aligned.m16n8k16.row.col.f32.bf16.bf16.f32 "                \
        "{%0,%1,%2,%3}, {%4,%5,%6,%7}, {%8,%9}, {%0,%1,%2,%3};\n"             \
        : "+f"((d)[0]), "+f"((d)[1]), "+f"((d)[2]), "+f"((d)[3])              \
        : "r"((a)[0]), "r"((a)[1]), "r"((a)[2]), "r"((a)[3]),                 \
          "r"((b)[0]), "r"((b)[1]))

// ---------------------------------------------------------------------------
// Kernel 1: fp32 -> bf16 conversion (unchanged, near HBM roofline)
// ---------------------------------------------------------------------------
__global__ void convert_kernel(const float* __restrict__ q, const float* __restrict__ m) {
    size_t i = (size_t)blockIdx.x * blockDim.x + threadIdx.x;
    size_t n4 = (size_t)BATCH * LSEQ * DDIM / 4;
    if (i >= n4) return;
    float4 vq = ((const float4*)q)[i];
    float4 vm = ((const float4*)m)[i];
    __nv_bfloat162* Q2 = (__nv_bfloat162*)g_Qb;
    __nv_bfloat162* M2 = (__nv_bfloat162*)g_Mb;
    Q2[2*i]   = __nv_bfloat162(__float2bfloat16(vq.x), __float2bfloat16(vq.y));
    Q2[2*i+1] = __nv_bfloat162(__float2bfloat16(vq.z), __float2bfloat16(vq.w));
    M2[2*i]   = __nv_bfloat162(__float2bfloat16(vm.x), __float2bfloat16(vm.y));
    M2[2*i+1] = __nv_bfloat162(__float2bfloat16(vm.z), __float2bfloat16(vm.w));
}

// ---------------------------------------------------------------------------
// Kernel 2: bf16 mma.sync GEMM, 128x128 tile, BK=32, 4-stage cp.async,
// ldmatrix fragment loads, 2 CTAs/SM. S[b,q,k] = dot(Q[b,q,:], M[b,k,:]) fp16.
// ---------------------------------------------------------------------------
#define BM 128
#define BN 128
#define BK 32
#define PITCH_B 80                         // bytes per smem row (64 used + 16 pad)
#define STG_SZ  (BM * PITCH_B)             // 10240 B per operand stage
#define NSTG 4
#define NKB (DDIM / BK)                    // 32
#define QK_DSMEM (2 * NSTG * STG_SZ)       // 81920 B

__global__ __launch_bounds__(256, 2) void qk_gemm_kernel() {
    extern __shared__ __align__(16) char dsm[];
    const uint32_t sb = smem_u32(dsm);

    const int tid   = threadIdx.x;
    const int lane  = tid & 31;
    const int warp  = tid >> 5;
    const int warpM = warp >> 2;           // 0..1  -> 64-row stripe
    const int warpN = warp & 3;            // 0..3  -> 32-col stripe
    const int g     = lane >> 2;
    const int t     = lane & 3;

    const int b     = blockIdx.z;
    const int mBase = blockIdx.y * BM;
    const int nBase = blockIdx.x * BN;
    const __nv_bfloat16* Qb = g_Qb + (size_t)b * LSEQ * DDIM;
    const __nv_bfloat16* Mb = g_Mb + (size_t)b * LSEQ * DDIM;

    uint32_t aS[NSTG], bS[NSTG];
    #pragma unroll
    for (int s = 0; s < NSTG; s++) {
        aS[s] = sb + s * STG_SZ;
        bS[s] = sb + NSTG * STG_SZ + s * STG_SZ;
    }

    // ldmatrix per-thread base offsets
    const int rowA = warpM * 64 + (lane & 7) + ((lane >> 3) & 1) * 8;
    const int colA = ((lane >> 4) & 1) * 8;          // k-elems
    const int rowB = warpN * 32 + (lane & 7) + ((lane >> 4) & 1) * 8;
    const int colB = ((lane >> 3) & 1) * 8;

    float acc[4][4][4];
    #pragma unroll
    for (int i = 0; i < 4; i++)
        #pragma unroll
        for (int j = 0; j < 4; j++)
            #pragma unroll
            for (int r = 0; r < 4; r++) acc[i][j][r] = 0.f;

    auto load_stage = [&](int s, int kb) {
        int k0 = kb * BK;
        #pragma unroll
        for (int i = 0; i < 2; i++) {                // 512 chunks per operand
            int j = tid + i * 256;
            int row = j >> 2;
            int c16 = (j & 3) * 16;                  // byte col
            cp_async16(aS[s] + row * PITCH_B + c16,
                       Qb + (size_t)(mBase + row) * DDIM + k0 + c16 / 2);
            cp_async16(bS[s] + row * PITCH_B + c16,
                       Mb + (size_t)(nBase + row) * DDIM + k0 + c16 / 2);
        }
        asm volatile("cp.async.commit_group;\n");
    };

    // prologue: 3 stages in flight
    load_stage(0, 0);
    load_stage(1, 1);
    load_stage(2, 2);

    for (int kb = 0; kb < NKB; kb++) {
        int s = kb & (NSTG - 1);
        if (kb < NKB - 2)      asm volatile("cp.async.wait_group 2;\n");
        else if (kb == NKB - 2) asm volatile("cp.async.wait_group 1;\n");
        else                    asm volatile("cp.async.wait_group 0;\n");
        __syncthreads();

        if (kb + 3 < NKB) load_stage((kb + 3) & (NSTG - 1), kb + 3);

        uint32_t aBase = aS[s] + rowA * PITCH_B + colA * 2;
        uint32_t bBase = bS[s] + rowB * PITCH_B + colB * 2;
        #pragma unroll
        for (int ks = 0; ks < 2; ks++) {             // two k16 slabs
            uint32_t af[4][4], bf[2][4];
            #pragma unroll
            for (int mt = 0; mt < 4; mt++)
                LDSM_X4(af[mt], aBase + mt * (16 * PITCH_B) + ks * 32);
            #pragma unroll
            for (int n2 = 0; n2 < 2; n2++)
                LDSM_X4(bf[n2], bBase + n2 * (16 * PITCH_B) + ks * 32);
            #pragma unroll
            for (int mt = 0; mt < 4; mt++)
                #pragma unroll
                for (int nt = 0; nt < 4; nt++)
                    MMA16816(acc[mt][nt], af[mt], &bf[nt >> 1][(nt & 1) * 2]);
        }
    }

    // Epilogue: write raw dot scores as fp16 (same mapping as validated R2 kernel)
    __half* Srow = g_S + (size_t)b * LSEQ * LSEQ;
    #pragma unroll
    for (int mt = 0; mt < 4; mt++) {
        #pragma unroll
        for (int nt = 0; nt < 4; nt++) {
            int row = mBase + warpM * 64 + mt * 16 + g;
            int col = nBase + warpN * 32 + nt * 8 + 2 * t;
            *(half2*)(Srow + (size_t)(row    ) * LSEQ + col) =
                __floats2half2_rn(acc[mt][nt][0], acc[mt][nt][1]);
            *(half2*)(Srow + (size_t)(row + 8) * LSEQ + col) =
                __floats2half2_rn(acc[mt][nt][2], acc[mt][nt][3]);
        }
    }
}

// ---------------------------------------------------------------------------
// Kernel 3: per-row refine (unchanged — known correct)
// ---------------------------------------------------------------------------
#define CAP 64
#define MARGIN 1.0f

__global__ __launch_bounds__(256) void refine_kernel(const float* __restrict__ Q,
                                                     const float* __restrict__ Mem,
                                                     float* __restrict__ Out) {
    const int b = blockIdx.y, q = blockIdx.x, tid = threadIdx.x;
    const __half* srow = g_S + ((size_t)b * LSEQ + q) * LSEQ;

    __shared__ float red[8];
    __shared__ int   s_cnt;
    __shared__ int   s_idx[CAP];
    __shared__ float s_dot[CAP];
    __shared__ float s_w[CAP];
    __shared__ float s_max;

    float mx = -1e30f;
    for (int k = tid; k < LSEQ; k += 256) mx = fmaxf(mx, __half2float(srow[k]));
    #pragma unroll
    for (int o = 16; o; o >>= 1) mx = fmaxf(mx, __shfl_xor_sync(0xffffffffu, mx, o));
    if ((tid & 31) == 0) red[tid >> 5] = mx;
    __syncthreads();
    if (tid < 32) {
        float v = (tid < 8) ? red[tid] : -1e30f;
        #pragma unroll
        for (int o = 4; o; o >>= 1) v = fmaxf(v, __shfl_xor_sync(0xffffffffu, v, o));
        if (tid == 0) { s_max = v; s_cnt = 0; }
    }
    __syncthreads();

    float thr = s_max - MARGIN;
    for (int k = tid; k < LSEQ; k += 256) {
        if (__half2float(srow[k]) >= thr) {
            int p = atomicAdd(&s_cnt, 1);
            if (p < CAP) s_idx[p] = k;
        }
    }
    __syncthreads();
    int nc = min(s_cnt, CAP);
    if (tid == 0) {
        for (int i = 1; i < nc; i++) {
            int v = s_idx[i], j = i - 1;
            while (j >= 0 && s_idx[j] > v) { s_idx[j + 1] = s_idx[j]; j--; }
            s_idx[j + 1] = v;
        }
    }
    __syncthreads();

    const float* qrow = Q + ((size_t)b * LSEQ + q) * DDIM;
    for (int j = 0; j < nc; j++) {
        const float* mrow = Mem + ((size_t)b * LSEQ + s_idx[j]) * DDIM;
        float p = 0.f;
        for (int d = tid; d < DDIM; d += 256) p += qrow[d] * mrow[d];
        #pragma unroll
        for (int o = 16; o; o >>= 1) p += __shfl_xor_sync(0xffffffffu, p, o);
        __syncthreads();
        if ((tid & 31) == 0) red[tid >> 5] = p;
        __syncthreads();
        if (tid == 0) {
            float s = 0.f;
            #pragma unroll
            for (int w = 0; w < 8; w++) s += red[w];
            s_dot[j] = s;
        }
    }
    __syncthreads();

    if (tid == 0) {
        float dm = -1e30f;
        for (int j = 0; j < nc; j++) dm = fmaxf(dm, s_dot[j]);
        float sum = 0.f;
        for (int j = 0; j < nc; j++) {
            float w = expf((s_dot[j] - dm) * TAW_INV);
            s_w[j] = w; sum += w;
        }
        float inv = 1.0f / sum;
        for (int j = 0; j < nc; j++) s_w[j] *= inv;
    }
    __syncthreads();

    float* orow = Out + ((size_t)b * LSEQ + q) * DDIM;
    for (int d = tid; d < DDIM; d += 256) {
        float a = 0.f;
        for (int j = 0; j < nc; j++)
            a += s_w[j] * Mem[((size_t)b * LSEQ + s_idx[j]) * DDIM + d];
        orow[d] = a;
    }
}

// ---------------------------------------------------------------------------
extern "C" void kernel_launch(void* const* d_in, const int* in_sizes, int n_in,
                              void* d_out, int out_size) {
    const float* q = (const float*)d_in[0];
    const float* m = (const float*)d_in[1];
    float* out = (float*)d_out;

    // Host-side attribute set (not a stream op -> capture-safe); needed for
    // 80KB dynamic smem.
    cudaFuncSetAttribute(qk_gemm_kernel,
                         cudaFuncAttributeMaxDynamicSharedMemorySize, QK_DSMEM);

    size_t n4 = (size_t)BATCH * LSEQ * DDIM / 4;
    convert_kernel<<<(unsigned)((n4 + 255) / 256), 256>>>(q, m);

    dim3 gg(LSEQ / BN, LSEQ / BM, BATCH);          // 16 x 16 x 8
    qk_gemm_kernel<<<gg, 256, QK_DSMEM>>>();

    dim3 rg(LSEQ, BATCH);
    refine_kernel<<<rg, 256>>>(q, m, out);
}